// round 2
// baseline (speedup 1.0000x reference)
#include <cuda_runtime.h>
#include <cstdint>

// Problem constants (fixed by the reference)
#define NV 65536
#define NB 8
#define FD 16
#define FS 9
#define NUM_SAMPLES (NV * NB)          // 524288
#define ATLAS_STRIDE (FD * FS * FS)    // 1296 floats per atlas entry
#define CH_STRIDE (FS * FS)            // 81 floats per channel

// One thread per (sample, channel). 16 threads per sample.
// Lanes 0..15 -> sample s, lanes 16..31 -> sample s+1 within each warp.
__global__ __launch_bounds__(256) void feature_texel_kernel(
    const float2* __restrict__ x,     // [NUM_SAMPLES] (raw x, y in [-1,1])
    const int*    __restrict__ inds,  // [NUM_SAMPLES]
    const float*  __restrict__ ft,    // [NUM_ATLAS * 1296]
    float*        __restrict__ out)   // [NUM_SAMPLES * FD]
{
    const int gtid   = blockIdx.x * blockDim.x + threadIdx.x;
    const int sample = gtid >> 4;        // /16
    const int c      = gtid & 15;        // channel

    if (sample >= NUM_SAMPLES) return;

    // Same-address reads across the 16 lanes of a sample -> L1 broadcast.
    const float2 xy  = __ldg(&x[sample]);
    const int    ind = __ldg(&inds[sample]);

    // Grid coords, matching the reference exactly.
    float gx = (xy.x + 1.0f) * 0.5f * (float)(FS - 1);
    float gy = (xy.y + 1.0f) * 0.5f * (float)(FS - 1);
    gx = fminf(fmaxf(gx, 0.0f), (float)(FS - 1));
    gy = fminf(fmaxf(gy, 0.0f), (float)(FS - 1));

    const float x0f = floorf(gx);
    const float y0f = floorf(gy);
    const float wx  = gx - x0f;
    const float wy  = gy - y0f;

    const int x0 = (int)x0f;
    const int y0 = (int)y0f;
    const int x1 = min(x0 + 1, FS - 1);
    const int y1 = min(y0 + 1, FS - 1);

    // 64-bit base computed once; texel offsets stay 32-bit.
    const float* __restrict__ tile =
        ft + ((size_t)ind * ATLAS_STRIDE + (size_t)c * CH_STRIDE);

    const int o00 = y0 * FS + x0;
    const int o01 = y0 * FS + x1;
    const int o10 = y1 * FS + x0;
    const int o11 = y1 * FS + x1;

    // 4 independent gathers -> MLP=4 per thread, front-batched by ptxas.
    const float v00 = __ldg(tile + o00);
    const float v01 = __ldg(tile + o01);
    const float v10 = __ldg(tile + o10);
    const float v11 = __ldg(tile + o11);

    const float top = v00 * (1.0f - wx) + v01 * wx;
    const float bot = v10 * (1.0f - wx) + v11 * wx;
    const float res = top * (1.0f - wy) + bot * wy;

    // Coalesced: 16 consecutive floats per sample, 64B per half-warp group.
    out[(size_t)sample * FD + c] = res;
}

extern "C" void kernel_launch(void* const* d_in, const int* in_sizes, int n_in,
                              void* d_out, int out_size)
{
    const float2* x    = (const float2*)d_in[0]; // (NV, NB, 2) f32
    const int*    inds = (const int*)d_in[1];    // (NV, NB) i32
    const float*  ft   = (const float*)d_in[2];  // (NUM_ATLAS, 16, 9, 9) f32
    float*        out  = (float*)d_out;          // (NV, NB, 16) f32

    const int total_threads = NUM_SAMPLES * FD;  // 8,388,608
    const int block = 256;
    const int grid  = (total_threads + block - 1) / block;
    feature_texel_kernel<<<grid, block>>>(x, inds, ft, out);
}